// round 2
// baseline (speedup 1.0000x reference)
#include <cuda_runtime.h>

#define BIN 256
#define IM 256
#define NPIX (IM * IM)          // 65536
#define NHIST 4                 // {inp,ref} x {b0,b1}

// Scratch: 4 histograms of 256x256 float = 1 MB.
// Zero-initialized at module load; re-zeroed by loss_kernel after each read,
// so every kernel_launch call (and every graph replay) starts from zeros.
__device__ float g_hist[NHIST * BIN * BIN];

// Triangular-kernel weight, numerics matching the reference exactly:
//   bias_k = 1 - 2k/256 (exact dyadic), a1 = u + bias_k, w = relu(1 - |a1|*255)
__device__ __forceinline__ float tri_w(float u, int k) {
    float a1 = u + (1.0f - (float)k * 0.0078125f);
    return fmaxf(0.0f, 1.0f - fabsf(a1) * 255.0f);
}

// ---------------------------------------------------------------------------
// Kernel 1: per-pixel scatter of the 2x2 outer-product patch.
// hist2d[b,j,r] = sum_hw hb_j(ch1) * ha_r(ch0)   (mean applied in loss)
// Each thread handles one (b, pixel) for BOTH input tensors.
// ---------------------------------------------------------------------------
__global__ void scatter_kernel(const float* __restrict__ inp,
                               const float* __restrict__ ref) {
    int idx = blockIdx.x * blockDim.x + threadIdx.x;
    int b = idx >> 16;          // batch
    int p = idx & (NPIX - 1);   // pixel

#pragma unroll
    for (int t = 0; t < 2; ++t) {
        const float* img = (t == 0) ? inp : ref;
        float xa = img[(b * 2 + 0) * NPIX + p];   // channel 0 -> r axis
        float xb = img[(b * 2 + 1) * NPIX + p];   // channel 1 -> j axis
        float ua = (xa + 1.0f) * 0.5f;
        float ub = (xb + 1.0f) * 0.5f;

        // support of the triangular kernel covers bins {floor(.), floor(.)+1}
        int ka = (int)floorf(ua * 128.0f + 128.0f);
        int kb = (int)floorf(ub * 128.0f + 128.0f);

        float wa0 = tri_w(ua, ka);
        float wa1 = tri_w(ua, ka + 1);
        float wb0 = tri_w(ub, kb);
        float wb1 = tri_w(ub, kb + 1);

        bool a1ok = (ka + 1) < BIN;   // bin 256 reachable only at u ~ 1
        bool b1ok = (kb + 1) < BIN;

        float* H = g_hist + (t * 2 + b) * BIN * BIN;
        float* row0 = H + kb * BIN;

        atomicAdd(row0 + ka, wb0 * wa0);
        if (a1ok)          atomicAdd(row0 + ka + 1, wb0 * wa1);
        if (b1ok) {
            float* row1 = row0 + BIN;
            atomicAdd(row1 + ka, wb1 * wa0);
            if (a1ok)      atomicAdd(row1 + ka + 1, wb1 * wa1);
        }
    }
}

// ---------------------------------------------------------------------------
// Kernel 2: Huber loss between the two (mean-normalized) histograms,
// float4-vectorized, and re-zero the histogram cells for the next call.
// out[b,0,j,r], 2*65536 elements -> 32768 float4 threads.
// ---------------------------------------------------------------------------
__global__ void loss_kernel(float* __restrict__ out) {
    int i = blockIdx.x * blockDim.x + threadIdx.x;   // float4 index
    if (i >= 2 * BIN * BIN / 4) return;
    int b   = i >> 14;                   // 16384 float4 per batch image
    int jr4 = i & (BIN * BIN / 4 - 1);

    float4* Hi = reinterpret_cast<float4*>(g_hist + (0 * 2 + b) * BIN * BIN);
    float4* Hg = reinterpret_cast<float4*>(g_hist + (1 * 2 + b) * BIN * BIN);

    float4 hi = Hi[jr4];
    float4 hg = Hg[jr4];

    const float4 z = make_float4(0.f, 0.f, 0.f, 0.f);
    Hi[jr4] = z;
    Hg[jr4] = z;

    const float inv = 1.0f / (float)NPIX;
    float4 r;
    {
        float m;
        m = fabsf(hi.x - hg.x) * inv; r.x = (m < 0.01f) ? 50.f * m * m : m - 0.005f;
        m = fabsf(hi.y - hg.y) * inv; r.y = (m < 0.01f) ? 50.f * m * m : m - 0.005f;
        m = fabsf(hi.z - hg.z) * inv; r.z = (m < 0.01f) ? 50.f * m * m : m - 0.005f;
        m = fabsf(hi.w - hg.w) * inv; r.w = (m < 0.01f) ? 50.f * m * m : m - 0.005f;
    }
    reinterpret_cast<float4*>(out)[i] = r;
}

// ---------------------------------------------------------------------------
extern "C" void kernel_launch(void* const* d_in, const int* in_sizes, int n_in,
                              void* d_out, int out_size) {
    const float* inp = (const float*)d_in[0];
    const float* ref = (const float*)d_in[1];
    float* out = (float*)d_out;

    scatter_kernel<<<2 * NPIX / 256, 256>>>(inp, ref);
    loss_kernel<<<(2 * BIN * BIN / 4) / 256, 256>>>(out);
}